// round 7
// baseline (speedup 1.0000x reference)
#include <cuda_runtime.h>

#ifndef M_PI_F
#define M_PI_F 3.14159265358979323846f
#endif

#define FDIM 512
#define NOUT 100
#define RB   4            // rows per warp
#define WPB  4            // warps per block (128 threads)

__device__ __forceinline__ void cp_async16(unsigned int saddr, const void* gaddr) {
    asm volatile("cp.async.cg.shared.global [%0], [%1], 16;" :: "r"(saddr), "l"(gaddr));
}
__device__ __forceinline__ void cp_commit() {
    asm volatile("cp.async.commit_group;" ::: "memory");
}
template <int N>
__device__ __forceinline__ void cp_wait() {
    asm volatile("cp.async.wait_group %0;" :: "n"(N) : "memory");
}

// Warp = 4 rows. Whole task prefetched up-front via cp.async (one DRAM-latency
// exposure per task, not per row). 12 reduction chains batched -> shuffle
// throughput-bound, not latency-bound. 20 warps/SM (5 blocks x 4 warps).
__global__ __launch_bounds__(128, 5)
void qnet_fused_kernel(const float* __restrict__ X,
                       const float* __restrict__ preW,
                       const float* __restrict__ preB,
                       const float* __restrict__ qp,
                       const float* __restrict__ postW,
                       const float* __restrict__ postB,
                       float* __restrict__ out,
                       int B)
{
    __shared__ float4 xring[WPB][RB][128];   // 4 warps x 4 rows x 2KB = 32KB

    const int tid  = threadIdx.x;
    const int wid  = tid >> 5;
    const int lane = tid & 31;
    const int wbase = (blockIdx.x * WPB + wid) * RB;
    if (wbase >= B) return;
    const int rows = min(RB, B - wbase);

    const float4* __restrict__ X4 = reinterpret_cast<const float4*>(X);

    // ---- issue ALL rows of this task up-front ----
    #pragma unroll
    for (int r = 0; r < RB; ++r) {
        const int grow = wbase + min(r, rows - 1);
        const float4* __restrict__ src = X4 + (size_t)grow * 128;
        #pragma unroll
        for (int k = 0; k < 4; ++k) {
            unsigned int sa = (unsigned int)__cvta_generic_to_shared(&xring[wid][r][lane + 32 * k]);
            cp_async16(sa, src + lane + 32 * k);
        }
        cp_commit();
    }

    // ---- pre_W in registers while loads fly ----
    const float4* __restrict__ W4 = reinterpret_cast<const float4*>(preW);
    float4 wa[4], wb[4], wc[4];
    #pragma unroll
    for (int k = 0; k < 4; ++k) {
        const int i = lane + 32 * k;
        wa[k] = __ldg(W4 + i);
        wb[k] = __ldg(W4 + 128 + i);
        wc[k] = __ldg(W4 + 256 + i);
    }

    // ---- dots: 12 accumulators (4 rows x 3) ----
    float dd0[RB], dd1[RB], dd2[RB];
    #pragma unroll
    for (int r = 0; r < RB; ++r) {
        if (r == 0)      cp_wait<3>();
        else if (r == 1) cp_wait<2>();
        else if (r == 2) cp_wait<1>();
        else             cp_wait<0>();
        __syncwarp();
        float d0 = 0.f, d1 = 0.f, d2 = 0.f;
        #pragma unroll
        for (int k = 0; k < 4; ++k) {
            const float4 xv = xring[wid][r][lane + 32 * k];
            d0 += xv.x * wa[k].x + xv.y * wa[k].y + xv.z * wa[k].z + xv.w * wa[k].w;
            d1 += xv.x * wb[k].x + xv.y * wb[k].y + xv.z * wb[k].z + xv.w * wb[k].w;
            d2 += xv.x * wc[k].x + xv.y * wc[k].y + xv.z * wc[k].z + xv.w * wc[k].w;
        }
        dd0[r] = d0; dd1[r] = d1; dd2[r] = d2;
    }

    // ---- 12 interleaved butterfly chains (throughput-bound) ----
    #pragma unroll
    for (int off = 16; off > 0; off >>= 1) {
        #pragma unroll
        for (int r = 0; r < RB; ++r) {
            dd0[r] += __shfl_xor_sync(0xFFFFFFFFu, dd0[r], off);
            dd1[r] += __shfl_xor_sync(0xFFFFFFFFu, dd1[r], off);
            dd2[r] += __shfl_xor_sync(0xFFFFFFFFu, dd2[r], off);
        }
    }

    // lane (l & 3) owns row (l & 3)
    const int myrow = lane & (RB - 1);
    float a0 = 0.f, a1 = 0.f, a2 = 0.f;
    #pragma unroll
    for (int r = 0; r < RB; ++r)
        if (myrow == r) { a0 = dd0[r]; a1 = dd1[r]; a2 = dd2[r]; }

    // ---- per-lane circuit ----
    const float t0 = tanhf(a0 + __ldg(preB + 0)) * (M_PI_F * 0.5f);
    const float t1 = tanhf(a1 + __ldg(preB + 1)) * (M_PI_F * 0.5f);
    const float t2 = tanhf(a2 + __ldg(preB + 2)) * (M_PI_F * 0.5f);

    float s[8];
    const float inv_sqrt8 = 0.3535533905932738f;
    #pragma unroll
    for (int i = 0; i < 8; ++i) s[i] = inv_sqrt8;

    auto ry0 = [&](float th) {
        float sn, cs; __sincosf(th * 0.5f, &sn, &cs);
        #pragma unroll
        for (int i = 0; i < 4; ++i) {
            float a = s[i], b = s[i + 4];
            s[i]     = cs * a - sn * b;
            s[i + 4] = sn * a + cs * b;
        }
    };
    auto ry1 = [&](float th) {
        float sn, cs; __sincosf(th * 0.5f, &sn, &cs);
        #pragma unroll
        for (int g = 0; g < 2; ++g)
            #pragma unroll
            for (int i = 0; i < 2; ++i) {
                int lo = g * 4 + i;
                float a = s[lo], b = s[lo + 2];
                s[lo]     = cs * a - sn * b;
                s[lo + 2] = sn * a + cs * b;
            }
    };
    auto ry2 = [&](float th) {
        float sn, cs; __sincosf(th * 0.5f, &sn, &cs);
        #pragma unroll
        for (int g = 0; g < 4; ++g) {
            int lo = g * 2;
            float a = s[lo], b = s[lo + 1];
            s[lo]     = cs * a - sn * b;
            s[lo + 1] = sn * a + cs * b;
        }
    };

    ry0(t0); ry1(t1); ry2(t2);

    #pragma unroll
    for (int k = 0; k < 2; ++k) {
        float tmp;
        tmp = s[4]; s[4] = s[6]; s[6] = tmp;   // CNOT(0,1)
        tmp = s[5]; s[5] = s[7]; s[7] = tmp;
        tmp = s[2]; s[2] = s[3]; s[3] = tmp;   // CNOT(1,2)
        tmp = s[6]; s[6] = s[7]; s[7] = tmp;
        ry0(__ldg(qp + 3 * (k + 1) + 0));
        ry1(__ldg(qp + 3 * (k + 1) + 1));
        ry2(__ldg(qp + 3 * (k + 1) + 2));
    }

    float p[8];
    #pragma unroll
    for (int i = 0; i < 8; ++i) p[i] = s[i] * s[i];

    const float z0 = (p[0] + p[1] + p[2] + p[3]) - (p[4] + p[5] + p[6] + p[7]);
    const float z1 = (p[0] + p[1] + p[4] + p[5]) - (p[2] + p[3] + p[6] + p[7]);
    const float z2 = (p[0] + p[2] + p[4] + p[6]) - (p[1] + p[3] + p[5] + p[7]);

    // ---- epilogue: 4 rows x 25 float4, fully contiguous stream ----
    const float4* __restrict__ pW4 = reinterpret_cast<const float4*>(postW);  // 75 float4
    const float4* __restrict__ pB4 = reinterpret_cast<const float4*>(postB);  // 25 float4
    float4* __restrict__ out4 = reinterpret_cast<float4*>(out) + (size_t)wbase * 25;
    const int lim = rows * 25;

    #pragma unroll
    for (int i = 0; i < 4; ++i) {
        const int f4  = i * 32 + lane;          // 0..127 ; valid < 100
        const int row = f4 / 25;
        const int g   = f4 - row * 25;
        const float zz0 = __shfl_sync(0xFFFFFFFFu, z0, row & (RB - 1));
        const float zz1 = __shfl_sync(0xFFFFFFFFu, z1, row & (RB - 1));
        const float zz2 = __shfl_sync(0xFFFFFFFFu, z2, row & (RB - 1));
        if (f4 < lim) {
            const float4 f0 = __ldg(pW4 + 3 * g + 0);
            const float4 f1 = __ldg(pW4 + 3 * g + 1);
            const float4 f2 = __ldg(pW4 + 3 * g + 2);
            const float4 bb = __ldg(pB4 + g);
            float4 o;
            o.x = zz0 * f0.x + zz1 * f0.y + zz2 * f0.z + bb.x;
            o.y = zz0 * f0.w + zz1 * f1.x + zz2 * f1.y + bb.y;
            o.z = zz0 * f1.z + zz1 * f1.w + zz2 * f2.x + bb.z;
            o.w = zz0 * f2.y + zz1 * f2.z + zz2 * f2.w + bb.w;
            __stcs(out4 + f4, o);
        }
    }
}

extern "C" void kernel_launch(void* const* d_in, const int* in_sizes, int n_in,
                              void* d_out, int out_size)
{
    const float* X     = (const float*)d_in[0]; // [B, 512]
    const float* preW  = (const float*)d_in[1]; // [3, 512]
    const float* preB  = (const float*)d_in[2]; // [3]
    const float* qp    = (const float*)d_in[3]; // [45]
    const float* postW = (const float*)d_in[4]; // [100, 3]
    const float* postB = (const float*)d_in[5]; // [100]
    float* out = (float*)d_out;                 // [B, 100]

    const int B = in_sizes[0] / FDIM;
    const int warps  = (B + RB - 1) / RB;
    const int blocks = (warps + WPB - 1) / WPB;

    qnet_fused_kernel<<<blocks, WPB * 32>>>(X, preW, preB, qp, postW, postB, out, B);
}

// round 8
// speedup vs baseline: 1.1730x; 1.1730x over previous
#include <cuda_runtime.h>

#ifndef M_PI_F
#define M_PI_F 3.14159265358979323846f
#endif

#define FDIM 512
#define NOUT 100
#define RB   8            // rows per warp
#define WPB  8            // warps per block (256 threads)
#define STAGES 4

__device__ __forceinline__ void cp_async16(unsigned int saddr, const void* gaddr) {
    asm volatile("cp.async.cg.shared.global [%0], [%1], 16;" :: "r"(saddr), "l"(gaddr));
}
__device__ __forceinline__ void cp_commit() {
    asm volatile("cp.async.commit_group;" ::: "memory");
}
template <int N>
__device__ __forceinline__ void cp_wait() {
    asm volatile("cp.async.wait_group %0;" :: "n"(N) : "memory");
}

// RB=8 amortization (R6) + batched end-of-task reduction (R7) + 4-deep ring:
//  - dot loop: wait + 4 LDS.128 + 12 FFMA per row, ZERO shuffles in loop
//  - 24 accumulators reduced once at task end via 24 interleaved butterfly
//    chains (throughput-bound, ~250cyc) instead of 8 serial 130cyc chains
//  - 3 rows (6KB) in flight per warp steady-state -> 96KB/SM at 16 warps
__global__ __launch_bounds__(256, 2)
void qnet_fused_kernel(const float* __restrict__ X,
                       const float* __restrict__ preW,
                       const float* __restrict__ preB,
                       const float* __restrict__ qp,
                       const float* __restrict__ postW,
                       const float* __restrict__ postB,
                       float* __restrict__ out,
                       int B)
{
    extern __shared__ float4 xring[];   // [WPB][STAGES][128] : 8*4*2KB = 64KB

    const int tid  = threadIdx.x;
    const int wid  = tid >> 5;
    const int lane = tid & 31;
    const int wbase = (blockIdx.x * WPB + wid) * RB;
    if (wbase >= B) return;
    const int rows = min(RB, B - wbase);

    float4* __restrict__ myring = xring + (size_t)wid * STAGES * 128;
    const float4* __restrict__ X4 = reinterpret_cast<const float4*>(X);

    auto issue = [&](int r) {
        const int grow = wbase + min(r, rows - 1);
        const float4* __restrict__ src = X4 + (size_t)grow * 128;
        float4* dst = myring + (r & (STAGES - 1)) * 128;
        #pragma unroll
        for (int k = 0; k < 4; ++k) {
            unsigned int sa = (unsigned int)__cvta_generic_to_shared(dst + lane + 32 * k);
            cp_async16(sa, src + lane + 32 * k);
        }
        cp_commit();
    };

    // prefetch 4 rows up-front
    issue(0); issue(1); issue(2); issue(3);

    // pre_W in registers while loads fly
    const float4* __restrict__ W4 = reinterpret_cast<const float4*>(preW);
    float4 wa[4], wb[4], wc[4];
    #pragma unroll
    for (int k = 0; k < 4; ++k) {
        const int i = lane + 32 * k;
        wa[k] = __ldg(W4 + i);
        wb[k] = __ldg(W4 + 128 + i);
        wc[k] = __ldg(W4 + 256 + i);
    }

    // ---- dot loop: no shuffles, 24 per-lane accumulators ----
    float dd0[RB], dd1[RB], dd2[RB];
    #pragma unroll
    for (int r = 0; r < RB; ++r) {
        if (r < 4)       cp_wait<3>();
        else if (r == 4) cp_wait<3>();
        else if (r == 5) cp_wait<2>();
        else if (r == 6) cp_wait<1>();
        else             cp_wait<0>();
        __syncwarp();

        const float4* xs = myring + (r & (STAGES - 1)) * 128;
        float d0 = 0.f, d1 = 0.f, d2 = 0.f;
        #pragma unroll
        for (int k = 0; k < 4; ++k) {
            const float4 xv = xs[lane + 32 * k];
            d0 += xv.x * wa[k].x + xv.y * wa[k].y + xv.z * wa[k].z + xv.w * wa[k].w;
            d1 += xv.x * wb[k].x + xv.y * wb[k].y + xv.z * wb[k].z + xv.w * wb[k].w;
            d2 += xv.x * wc[k].x + xv.y * wc[k].y + xv.z * wc[k].z + xv.w * wc[k].w;
        }
        dd0[r] = d0; dd1[r] = d1; dd2[r] = d2;

        if (r + STAGES < RB) issue(r + STAGES);
    }

    // ---- batched reduction: 24 interleaved butterfly chains ----
    #pragma unroll
    for (int off = 16; off > 0; off >>= 1) {
        #pragma unroll
        for (int r = 0; r < RB; ++r) {
            dd0[r] += __shfl_xor_sync(0xFFFFFFFFu, dd0[r], off);
            dd1[r] += __shfl_xor_sync(0xFFFFFFFFu, dd1[r], off);
            dd2[r] += __shfl_xor_sync(0xFFFFFFFFu, dd2[r], off);
        }
    }

    // lane (l & 7) owns row (l & 7): compile-time predicated selects
    const int myrow = lane & 7;
    float a0 = 0.f, a1 = 0.f, a2 = 0.f;
    #pragma unroll
    for (int r = 0; r < RB; ++r)
        if (myrow == r) { a0 = dd0[r]; a1 = dd1[r]; a2 = dd2[r]; }

    // ---- per-lane circuit (8 rows per warp-instruction) ----
    const float t0 = tanhf(a0 + __ldg(preB + 0)) * (M_PI_F * 0.5f);
    const float t1 = tanhf(a1 + __ldg(preB + 1)) * (M_PI_F * 0.5f);
    const float t2 = tanhf(a2 + __ldg(preB + 2)) * (M_PI_F * 0.5f);

    float s[8];
    const float inv_sqrt8 = 0.3535533905932738f;
    #pragma unroll
    for (int i = 0; i < 8; ++i) s[i] = inv_sqrt8;

    auto ry0 = [&](float th) {
        float sn, cs; __sincosf(th * 0.5f, &sn, &cs);
        #pragma unroll
        for (int i = 0; i < 4; ++i) {
            float a = s[i], b = s[i + 4];
            s[i]     = cs * a - sn * b;
            s[i + 4] = sn * a + cs * b;
        }
    };
    auto ry1 = [&](float th) {
        float sn, cs; __sincosf(th * 0.5f, &sn, &cs);
        #pragma unroll
        for (int g = 0; g < 2; ++g)
            #pragma unroll
            for (int i = 0; i < 2; ++i) {
                int lo = g * 4 + i;
                float a = s[lo], b = s[lo + 2];
                s[lo]     = cs * a - sn * b;
                s[lo + 2] = sn * a + cs * b;
            }
    };
    auto ry2 = [&](float th) {
        float sn, cs; __sincosf(th * 0.5f, &sn, &cs);
        #pragma unroll
        for (int g = 0; g < 4; ++g) {
            int lo = g * 2;
            float a = s[lo], b = s[lo + 1];
            s[lo]     = cs * a - sn * b;
            s[lo + 1] = sn * a + cs * b;
        }
    };

    ry0(t0); ry1(t1); ry2(t2);

    #pragma unroll
    for (int k = 0; k < 2; ++k) {
        float tmp;
        tmp = s[4]; s[4] = s[6]; s[6] = tmp;   // CNOT(0,1)
        tmp = s[5]; s[5] = s[7]; s[7] = tmp;
        tmp = s[2]; s[2] = s[3]; s[3] = tmp;   // CNOT(1,2)
        tmp = s[6]; s[6] = s[7]; s[7] = tmp;
        ry0(__ldg(qp + 3 * (k + 1) + 0));
        ry1(__ldg(qp + 3 * (k + 1) + 1));
        ry2(__ldg(qp + 3 * (k + 1) + 2));
    }

    float p[8];
    #pragma unroll
    for (int i = 0; i < 8; ++i) p[i] = s[i] * s[i];

    const float z0 = (p[0] + p[1] + p[2] + p[3]) - (p[4] + p[5] + p[6] + p[7]);
    const float z1 = (p[0] + p[1] + p[4] + p[5]) - (p[2] + p[3] + p[6] + p[7]);
    const float z2 = (p[0] + p[2] + p[4] + p[6]) - (p[1] + p[3] + p[5] + p[7]);

    // ---- epilogue: 8 rows x 25 float4, fully contiguous stream ----
    const float4* __restrict__ pW4 = reinterpret_cast<const float4*>(postW);  // 75 float4
    const float4* __restrict__ pB4 = reinterpret_cast<const float4*>(postB);  // 25 float4
    float4* __restrict__ out4 = reinterpret_cast<float4*>(out) + (size_t)wbase * 25;
    const int lim = rows * 25;

    #pragma unroll
    for (int i = 0; i < 7; ++i) {
        const int f4  = i * 32 + lane;          // 0..223 ; valid < 200
        const int row = f4 / 25;
        const int g   = f4 - row * 25;
        const float zz0 = __shfl_sync(0xFFFFFFFFu, z0, row & 7);
        const float zz1 = __shfl_sync(0xFFFFFFFFu, z1, row & 7);
        const float zz2 = __shfl_sync(0xFFFFFFFFu, z2, row & 7);
        if (f4 < lim) {
            const float4 f0 = __ldg(pW4 + 3 * g + 0);
            const float4 f1 = __ldg(pW4 + 3 * g + 1);
            const float4 f2 = __ldg(pW4 + 3 * g + 2);
            const float4 bb = __ldg(pB4 + g);
            float4 o;
            o.x = zz0 * f0.x + zz1 * f0.y + zz2 * f0.z + bb.x;
            o.y = zz0 * f0.w + zz1 * f1.x + zz2 * f1.y + bb.y;
            o.z = zz0 * f1.z + zz1 * f1.w + zz2 * f2.x + bb.z;
            o.w = zz0 * f2.y + zz1 * f2.z + zz2 * f2.w + bb.w;
            __stcs(out4 + f4, o);
        }
    }
}

extern "C" void kernel_launch(void* const* d_in, const int* in_sizes, int n_in,
                              void* d_out, int out_size)
{
    const float* X     = (const float*)d_in[0]; // [B, 512]
    const float* preW  = (const float*)d_in[1]; // [3, 512]
    const float* preB  = (const float*)d_in[2]; // [3]
    const float* qp    = (const float*)d_in[3]; // [45]
    const float* postW = (const float*)d_in[4]; // [100, 3]
    const float* postB = (const float*)d_in[5]; // [100]
    float* out = (float*)d_out;                 // [B, 100]

    const int B = in_sizes[0] / FDIM;
    const int warps  = (B + RB - 1) / RB;
    const int blocks = (warps + WPB - 1) / WPB;

    const int smem = WPB * STAGES * 128 * sizeof(float4);   // 64KB dynamic
    static int configured = 0;
    if (!configured) {
        cudaFuncSetAttribute(qnet_fused_kernel,
                             cudaFuncAttributeMaxDynamicSharedMemorySize, smem);
        configured = 1;
    }

    qnet_fused_kernel<<<blocks, WPB * 32, smem>>>(X, preW, preB, qp, postW, postB, out, B);
}

// round 10
// speedup vs baseline: 1.1870x; 1.0119x over previous
#include <cuda_runtime.h>

#ifndef M_PI_F
#define M_PI_F 3.14159265358979323846f
#endif

#define FDIM 512
#define NOUT 100
#define RB   8            // rows per warp
#define WPB  4            // warps per block (128 threads)
#define STAGES 4

__device__ __forceinline__ void cp_async16(unsigned int saddr, const void* gaddr) {
    asm volatile("cp.async.cg.shared.global [%0], [%1], 16;" :: "r"(saddr), "l"(gaddr));
}
__device__ __forceinline__ void cp_commit() {
    asm volatile("cp.async.commit_group;" ::: "memory");
}
template <int N>
__device__ __forceinline__ void cp_wait() {
    asm volatile("cp.async.wait_group %0;" :: "n"(N) : "memory");
}
// Packed dual-FMA (FFMA2) — PTX-only form.
__device__ __forceinline__ unsigned long long ffma2(unsigned long long a,
                                                    unsigned long long b,
                                                    unsigned long long c) {
    unsigned long long d;
    asm("fma.rn.f32x2 %0, %1, %2, %3;" : "=l"(d) : "l"(a), "l"(b), "l"(c));
    return d;
}
__device__ __forceinline__ float f32x2_hsum(unsigned long long v) {
    float lo, hi;
    asm("mov.b64 {%0, %1}, %2;" : "=f"(lo), "=f"(hi) : "l"(v));
    return lo + hi;
}
__device__ __forceinline__ float fast_tanh(float x) {
    return 1.0f - 2.0f / (__expf(2.0f * x) + 1.0f);
}

// R8 memory structure + instruction surgery:
//  - FFMA2 packed dot (24 packed FMA/row instead of 48 FFMA)
//  - two-phase merge reduction: per-row butterfly(16,8) + select into 6 chains,
//    then butterfly(4,2,1) on 6 chains (165 inst vs 240; dd regs 24 -> 6)
//  - fast exp-based tanh
//  - 128-thread blocks, 32KB static smem, launch_bounds(128,5) -> ~20 warps/SM
__global__ __launch_bounds__(128, 5)
void qnet_fused_kernel(const float* __restrict__ X,
                       const float* __restrict__ preW,
                       const float* __restrict__ preB,
                       const float* __restrict__ qp,
                       const float* __restrict__ postW,
                       const float* __restrict__ postB,
                       float* __restrict__ out,
                       int B)
{
    __shared__ float4 xring[WPB][STAGES][128];   // 32KB static

    const int tid  = threadIdx.x;
    const int wid  = tid >> 5;
    const int lane = tid & 31;
    const int wbase = (blockIdx.x * WPB + wid) * RB;
    if (wbase >= B) return;
    const int rows = min(RB, B - wbase);

    const float4* __restrict__ X4 = reinterpret_cast<const float4*>(X);

    auto issue = [&](int r) {
        const int grow = wbase + min(r, rows - 1);
        const float4* __restrict__ src = X4 + (size_t)grow * 128;
        float4* dst = &xring[wid][r & (STAGES - 1)][0];
        #pragma unroll
        for (int k = 0; k < 4; ++k) {
            unsigned int sa = (unsigned int)__cvta_generic_to_shared(dst + lane + 32 * k);
            cp_async16(sa, src + lane + 32 * k);
        }
        cp_commit();
    };

    issue(0); issue(1); issue(2); issue(3);

    // pre_W in registers as packed f32x2 (48 regs), loaded while cp.async flies
    const ulonglong2* __restrict__ Wp = reinterpret_cast<const ulonglong2*>(preW);
    unsigned long long w0p[8], w1p[8], w2p[8];
    #pragma unroll
    for (int k = 0; k < 4; ++k) {
        const int i = lane + 32 * k;
        ulonglong2 t0 = __ldg(Wp + i);
        ulonglong2 t1 = __ldg(Wp + 128 + i);
        ulonglong2 t2 = __ldg(Wp + 256 + i);
        w0p[2 * k] = t0.x; w0p[2 * k + 1] = t0.y;
        w1p[2 * k] = t1.x; w1p[2 * k + 1] = t1.y;
        w2p[2 * k] = t2.x; w2p[2 * k + 1] = t2.y;
    }

    const int grp = lane >> 3;     // 0..3 : which row this lane's chains track

    // 6 persistent chains: var x {rows 0-3 (a), rows 4-7 (b)}
    float c0a = 0.f, c1a = 0.f, c2a = 0.f;
    float c0b = 0.f, c1b = 0.f, c2b = 0.f;

    #pragma unroll
    for (int r = 0; r < RB; ++r) {
        if (r < 5)       cp_wait<3>();
        else if (r == 5) cp_wait<2>();
        else if (r == 6) cp_wait<1>();
        else             cp_wait<0>();
        __syncwarp();

        const ulonglong2* xs = reinterpret_cast<const ulonglong2*>(
            &xring[wid][r & (STAGES - 1)][0]);
        unsigned long long acc0 = 0, acc1 = 0, acc2 = 0;
        #pragma unroll
        for (int k = 0; k < 4; ++k) {
            const ulonglong2 xv = xs[lane + 32 * k];
            acc0 = ffma2(xv.x, w0p[2 * k],     acc0);
            acc0 = ffma2(xv.y, w0p[2 * k + 1], acc0);
            acc1 = ffma2(xv.x, w1p[2 * k],     acc1);
            acc1 = ffma2(xv.y, w1p[2 * k + 1], acc1);
            acc2 = ffma2(xv.x, w2p[2 * k],     acc2);
            acc2 = ffma2(xv.y, w2p[2 * k + 1], acc2);
        }
        if (r + STAGES < RB) issue(r + STAGES);

        float v0 = f32x2_hsum(acc0);
        float v1 = f32x2_hsum(acc1);
        float v2 = f32x2_hsum(acc2);

        // phase-1: partial butterfly (offsets 16, 8) -> per-(lane%8) partials
        v0 += __shfl_xor_sync(0xFFFFFFFFu, v0, 16);
        v1 += __shfl_xor_sync(0xFFFFFFFFu, v1, 16);
        v2 += __shfl_xor_sync(0xFFFFFFFFu, v2, 16);
        v0 += __shfl_xor_sync(0xFFFFFFFFu, v0, 8);
        v1 += __shfl_xor_sync(0xFFFFFFFFu, v1, 8);
        v2 += __shfl_xor_sync(0xFFFFFFFFu, v2, 8);

        // select row r's partial into the chain keyed by lane-group
        const bool g = (grp == (r & 3));
        if (r < 4) {
            c0a = g ? v0 : c0a;  c1a = g ? v1 : c1a;  c2a = g ? v2 : c2a;
        } else {
            c0b = g ? v0 : c0b;  c1b = g ? v1 : c1b;  c2b = g ? v2 : c2b;
        }
    }

    // phase-2: finish reduction on 6 chains (offsets 4, 2, 1)
    #pragma unroll
    for (int off = 4; off > 0; off >>= 1) {
        c0a += __shfl_xor_sync(0xFFFFFFFFu, c0a, off);
        c1a += __shfl_xor_sync(0xFFFFFFFFu, c1a, off);
        c2a += __shfl_xor_sync(0xFFFFFFFFu, c2a, off);
        c0b += __shfl_xor_sync(0xFFFFFFFFu, c0b, off);
        c1b += __shfl_xor_sync(0xFFFFFFFFu, c1b, off);
        c2b += __shfl_xor_sync(0xFFFFFFFFu, c2b, off);
    }

    // placement: lane (l&7) takes row (l&7); group base lane (mr&3)*8 holds it
    const int mr  = lane & 7;
    const int src = (mr & 3) << 3;
    const float xa0 = __shfl_sync(0xFFFFFFFFu, c0a, src);
    const float xb0 = __shfl_sync(0xFFFFFFFFu, c0b, src);
    const float xa1 = __shfl_sync(0xFFFFFFFFu, c1a, src);
    const float xb1 = __shfl_sync(0xFFFFFFFFu, c1b, src);
    const float xa2 = __shfl_sync(0xFFFFFFFFu, c2a, src);
    const float xb2 = __shfl_sync(0xFFFFFFFFu, c2b, src);
    const float a0 = (mr < 4) ? xa0 : xb0;
    const float a1 = (mr < 4) ? xa1 : xb1;
    const float a2 = (mr < 4) ? xa2 : xb2;

    // ---- per-lane circuit (8 rows per warp-instruction) ----
    const float t0 = fast_tanh(a0 + __ldg(preB + 0)) * (M_PI_F * 0.5f);
    const float t1 = fast_tanh(a1 + __ldg(preB + 1)) * (M_PI_F * 0.5f);
    const float t2 = fast_tanh(a2 + __ldg(preB + 2)) * (M_PI_F * 0.5f);

    float s[8];
    const float inv_sqrt8 = 0.3535533905932738f;
    #pragma unroll
    for (int i = 0; i < 8; ++i) s[i] = inv_sqrt8;

    auto ry0 = [&](float th) {
        float sn, cs; __sincosf(th * 0.5f, &sn, &cs);
        #pragma unroll
        for (int i = 0; i < 4; ++i) {
            float a = s[i], b = s[i + 4];
            s[i]     = cs * a - sn * b;
            s[i + 4] = sn * a + cs * b;
        }
    };
    auto ry1 = [&](float th) {
        float sn, cs; __sincosf(th * 0.5f, &sn, &cs);
        #pragma unroll
        for (int g2 = 0; g2 < 2; ++g2)
            #pragma unroll
            for (int i = 0; i < 2; ++i) {
                int lo = g2 * 4 + i;
                float a = s[lo], b = s[lo + 2];
                s[lo]     = cs * a - sn * b;
                s[lo + 2] = sn * a + cs * b;
            }
    };
    auto ry2 = [&](float th) {
        float sn, cs; __sincosf(th * 0.5f, &sn, &cs);
        #pragma unroll
        for (int g2 = 0; g2 < 4; ++g2) {
            int lo = g2 * 2;
            float a = s[lo], b = s[lo + 1];
            s[lo]     = cs * a - sn * b;
            s[lo + 1] = sn * a + cs * b;
        }
    };

    ry0(t0); ry1(t1); ry2(t2);

    #pragma unroll
    for (int k = 0; k < 2; ++k) {
        float tmp;
        tmp = s[4]; s[4] = s[6]; s[6] = tmp;   // CNOT(0,1)
        tmp = s[5]; s[5] = s[7]; s[7] = tmp;
        tmp = s[2]; s[2] = s[3]; s[3] = tmp;   // CNOT(1,2)
        tmp = s[6]; s[6] = s[7]; s[7] = tmp;
        ry0(__ldg(qp + 3 * (k + 1) + 0));
        ry1(__ldg(qp + 3 * (k + 1) + 1));
        ry2(__ldg(qp + 3 * (k + 1) + 2));
    }

    float p[8];
    #pragma unroll
    for (int i = 0; i < 8; ++i) p[i] = s[i] * s[i];

    const float z0 = (p[0] + p[1] + p[2] + p[3]) - (p[4] + p[5] + p[6] + p[7]);
    const float z1 = (p[0] + p[1] + p[4] + p[5]) - (p[2] + p[3] + p[6] + p[7]);
    const float z2 = (p[0] + p[2] + p[4] + p[6]) - (p[1] + p[3] + p[5] + p[7]);

    // ---- epilogue: 8 rows x 25 float4, fully contiguous stream ----
    const float4* __restrict__ pW4 = reinterpret_cast<const float4*>(postW);
    const float4* __restrict__ pB4 = reinterpret_cast<const float4*>(postB);
    float4* __restrict__ out4 = reinterpret_cast<float4*>(out) + (size_t)wbase * 25;
    const int lim = rows * 25;

    #pragma unroll
    for (int i = 0; i < 7; ++i) {
        const int f4  = i * 32 + lane;          // 0..223 ; valid < 200
        const int row = f4 / 25;
        const int g2  = f4 - row * 25;
        const float zz0 = __shfl_sync(0xFFFFFFFFu, z0, row & 7);
        const float zz1 = __shfl_sync(0xFFFFFFFFu, z1, row & 7);
        const float zz2 = __shfl_sync(0xFFFFFFFFu, z2, row & 7);
        if (f4 < lim) {
            const float4 f0 = __ldg(pW4 + 3 * g2 + 0);
            const float4 f1 = __ldg(pW4 + 3 * g2 + 1);
            const float4 f2 = __ldg(pW4 + 3 * g2 + 2);
            const float4 bb = __ldg(pB4 + g2);
            float4 o;
            o.x = zz0 * f0.x + zz1 * f0.y + zz2 * f0.z + bb.x;
            o.y = zz0 * f0.w + zz1 * f1.x + zz2 * f1.y + bb.y;
            o.z = zz0 * f1.z + zz1 * f1.w + zz2 * f2.x + bb.z;
            o.w = zz0 * f2.y + zz1 * f2.z + zz2 * f2.w + bb.w;
            __stcs(out4 + f4, o);
        }
    }
}

extern "C" void kernel_launch(void* const* d_in, const int* in_sizes, int n_in,
                              void* d_out, int out_size)
{
    const float* X     = (const float*)d_in[0]; // [B, 512]
    const float* preW  = (const float*)d_in[1]; // [3, 512]
    const float* preB  = (const float*)d_in[2]; // [3]
    const float* qp    = (const float*)d_in[3]; // [45]
    const float* postW = (const float*)d_in[4]; // [100, 3]
    const float* postB = (const float*)d_in[5]; // [100]
    float* out = (float*)d_out;                 // [B, 100]

    const int B = in_sizes[0] / FDIM;
    const int warps  = (B + RB - 1) / RB;
    const int blocks = (warps + WPB - 1) / WPB;

    qnet_fused_kernel<<<blocks, WPB * 32>>>(X, preW, preB, qp, postW, postB, out, B);
}

// round 11
// speedup vs baseline: 1.1892x; 1.0018x over previous
#include <cuda_runtime.h>

#ifndef M_PI_F
#define M_PI_F 3.14159265358979323846f
#endif

#define FDIM 512
#define NOUT 100
#define RB   8             // rows per task
#define TPW  4             // tasks per warp
#define CHUNK (RB * TPW)   // 32 rows per warp
#define WPB  4             // warps per block (128 threads)
#define STAGES 4

__device__ __forceinline__ void cp_async16(unsigned int saddr, const void* gaddr) {
    asm volatile("cp.async.cg.shared.global [%0], [%1], 16;" :: "r"(saddr), "l"(gaddr));
}
__device__ __forceinline__ void cp_commit() {
    asm volatile("cp.async.commit_group;" ::: "memory");
}
template <int N>
__device__ __forceinline__ void cp_wait() {
    asm volatile("cp.async.wait_group %0;" :: "n"(N) : "memory");
}
__device__ __forceinline__ unsigned long long ffma2(unsigned long long a,
                                                    unsigned long long b,
                                                    unsigned long long c) {
    unsigned long long d;
    asm("fma.rn.f32x2 %0, %1, %2, %3;" : "=l"(d) : "l"(a), "l"(b), "l"(c));
    return d;
}
__device__ __forceinline__ float f32x2_hsum(unsigned long long v) {
    float lo, hi;
    asm("mov.b64 {%0, %1}, %2;" : "=f"(lo), "=f"(hi) : "l"(v));
    return lo + hi;
}
__device__ __forceinline__ float fast_tanh(float x) {
    return 1.0f - 2.0f / (__expf(2.0f * x) + 1.0f);
}

// Cross-task pipelining: each warp owns 32 consecutive rows (4 tasks x 8).
// The cp.async ring runs CONTINUOUSLY across task boundaries, so the next
// task's 4 rows (8KB) are in flight while this task's reduce/circuit/epilogue
// executes -> DRAM request duty cycle ~100% (was ~55%: dot-loop-only).
// Prolog (weights/biases/qparams) hoisted to once per warp.
__global__ __launch_bounds__(128, 5)
void qnet_fused_kernel(const float* __restrict__ X,
                       const float* __restrict__ preW,
                       const float* __restrict__ preB,
                       const float* __restrict__ qp,
                       const float* __restrict__ postW,
                       const float* __restrict__ postB,
                       float* __restrict__ out,
                       int B)
{
    __shared__ float4 xring[WPB][STAGES][128];   // 32KB static

    const int tid  = threadIdx.x;
    const int wid  = tid >> 5;
    const int lane = tid & 31;
    const int wbase = (blockIdx.x * WPB + wid) * CHUNK;
    if (wbase >= B) return;
    const int total = min(CHUNK, B - wbase);

    const float4* __restrict__ X4 = reinterpret_cast<const float4*>(X);

    auto issue = [&](int i) {
        const int grow = wbase + min(i, total - 1);
        const float4* __restrict__ src = X4 + (size_t)grow * 128;
        float4* dst = &xring[wid][i & (STAGES - 1)][0];
        #pragma unroll
        for (int k = 0; k < 4; ++k) {
            unsigned int sa = (unsigned int)__cvta_generic_to_shared(dst + lane + 32 * k);
            cp_async16(sa, src + lane + 32 * k);
        }
        cp_commit();
    };

    issue(0); issue(1); issue(2); issue(3);

    // ---- once-per-warp prolog: weights + biases + qparams ----
    const ulonglong2* __restrict__ Wp = reinterpret_cast<const ulonglong2*>(preW);
    unsigned long long w0p[8], w1p[8], w2p[8];
    #pragma unroll
    for (int k = 0; k < 4; ++k) {
        const int i = lane + 32 * k;
        ulonglong2 q0 = __ldg(Wp + i);
        ulonglong2 q1 = __ldg(Wp + 128 + i);
        ulonglong2 q2 = __ldg(Wp + 256 + i);
        w0p[2 * k] = q0.x; w0p[2 * k + 1] = q0.y;
        w1p[2 * k] = q1.x; w1p[2 * k + 1] = q1.y;
        w2p[2 * k] = q2.x; w2p[2 * k + 1] = q2.y;
    }
    const float pb0 = __ldg(preB + 0), pb1 = __ldg(preB + 1), pb2 = __ldg(preB + 2);
    float qw[6];
    #pragma unroll
    for (int j = 0; j < 6; ++j) qw[j] = __ldg(qp + 3 + j);   // rows 1..2

    const int grp = lane >> 3;
    const int mr  = lane & 7;
    const int srcl = (mr & 3) << 3;

    const float4* __restrict__ pW4 = reinterpret_cast<const float4*>(postW);
    const float4* __restrict__ pB4 = reinterpret_cast<const float4*>(postB);

    #pragma unroll
    for (int t = 0; t < TPW; ++t) {
        // 6 persistent chains (each lane's chains fully rewritten every task)
        float c0a = 0.f, c1a = 0.f, c2a = 0.f;
        float c0b = 0.f, c1b = 0.f, c2b = 0.f;

        #pragma unroll
        for (int r = 0; r < RB; ++r) {
            const int i = t * RB + r;
            if (i < CHUNK - 3)       cp_wait<3>();
            else if (i == CHUNK - 3) cp_wait<2>();
            else if (i == CHUNK - 2) cp_wait<1>();
            else                     cp_wait<0>();
            __syncwarp();

            const ulonglong2* xs = reinterpret_cast<const ulonglong2*>(
                &xring[wid][i & (STAGES - 1)][0]);
            unsigned long long acc0 = 0, acc1 = 0, acc2 = 0;
            #pragma unroll
            for (int k = 0; k < 4; ++k) {
                const ulonglong2 xv = xs[lane + 32 * k];
                acc0 = ffma2(xv.x, w0p[2 * k],     acc0);
                acc0 = ffma2(xv.y, w0p[2 * k + 1], acc0);
                acc1 = ffma2(xv.x, w1p[2 * k],     acc1);
                acc1 = ffma2(xv.y, w1p[2 * k + 1], acc1);
                acc2 = ffma2(xv.x, w2p[2 * k],     acc2);
                acc2 = ffma2(xv.y, w2p[2 * k + 1], acc2);
            }
            if (i + STAGES < CHUNK) issue(i + STAGES);   // crosses task boundary

            float v0 = f32x2_hsum(acc0);
            float v1 = f32x2_hsum(acc1);
            float v2 = f32x2_hsum(acc2);

            v0 += __shfl_xor_sync(0xFFFFFFFFu, v0, 16);
            v1 += __shfl_xor_sync(0xFFFFFFFFu, v1, 16);
            v2 += __shfl_xor_sync(0xFFFFFFFFu, v2, 16);
            v0 += __shfl_xor_sync(0xFFFFFFFFu, v0, 8);
            v1 += __shfl_xor_sync(0xFFFFFFFFu, v1, 8);
            v2 += __shfl_xor_sync(0xFFFFFFFFu, v2, 8);

            const bool g = (grp == (r & 3));
            if (r < 4) {
                c0a = g ? v0 : c0a;  c1a = g ? v1 : c1a;  c2a = g ? v2 : c2a;
            } else {
                c0b = g ? v0 : c0b;  c1b = g ? v1 : c1b;  c2b = g ? v2 : c2b;
            }
        }

        #pragma unroll
        for (int off = 4; off > 0; off >>= 1) {
            c0a += __shfl_xor_sync(0xFFFFFFFFu, c0a, off);
            c1a += __shfl_xor_sync(0xFFFFFFFFu, c1a, off);
            c2a += __shfl_xor_sync(0xFFFFFFFFu, c2a, off);
            c0b += __shfl_xor_sync(0xFFFFFFFFu, c0b, off);
            c1b += __shfl_xor_sync(0xFFFFFFFFu, c1b, off);
            c2b += __shfl_xor_sync(0xFFFFFFFFu, c2b, off);
        }

        const float xa0 = __shfl_sync(0xFFFFFFFFu, c0a, srcl);
        const float xb0 = __shfl_sync(0xFFFFFFFFu, c0b, srcl);
        const float xa1 = __shfl_sync(0xFFFFFFFFu, c1a, srcl);
        const float xb1 = __shfl_sync(0xFFFFFFFFu, c1b, srcl);
        const float xa2 = __shfl_sync(0xFFFFFFFFu, c2a, srcl);
        const float xb2 = __shfl_sync(0xFFFFFFFFu, c2b, srcl);
        const float a0 = (mr < 4) ? xa0 : xb0;
        const float a1 = (mr < 4) ? xa1 : xb1;
        const float a2 = (mr < 4) ? xa2 : xb2;

        // ---- per-lane circuit ----
        const float t0 = fast_tanh(a0 + pb0) * (M_PI_F * 0.5f);
        const float t1 = fast_tanh(a1 + pb1) * (M_PI_F * 0.5f);
        const float t2 = fast_tanh(a2 + pb2) * (M_PI_F * 0.5f);

        float s[8];
        const float inv_sqrt8 = 0.3535533905932738f;
        #pragma unroll
        for (int i = 0; i < 8; ++i) s[i] = inv_sqrt8;

        auto ry0 = [&](float th) {
            float sn, cs; __sincosf(th * 0.5f, &sn, &cs);
            #pragma unroll
            for (int i = 0; i < 4; ++i) {
                float a = s[i], b = s[i + 4];
                s[i]     = cs * a - sn * b;
                s[i + 4] = sn * a + cs * b;
            }
        };
        auto ry1 = [&](float th) {
            float sn, cs; __sincosf(th * 0.5f, &sn, &cs);
            #pragma unroll
            for (int g2 = 0; g2 < 2; ++g2)
                #pragma unroll
                for (int i = 0; i < 2; ++i) {
                    int lo = g2 * 4 + i;
                    float a = s[lo], b = s[lo + 2];
                    s[lo]     = cs * a - sn * b;
                    s[lo + 2] = sn * a + cs * b;
                }
        };
        auto ry2 = [&](float th) {
            float sn, cs; __sincosf(th * 0.5f, &sn, &cs);
            #pragma unroll
            for (int g2 = 0; g2 < 4; ++g2) {
                int lo = g2 * 2;
                float a = s[lo], b = s[lo + 1];
                s[lo]     = cs * a - sn * b;
                s[lo + 1] = sn * a + cs * b;
            }
        };

        ry0(t0); ry1(t1); ry2(t2);

        #pragma unroll
        for (int k = 0; k < 2; ++k) {
            float tmp;
            tmp = s[4]; s[4] = s[6]; s[6] = tmp;   // CNOT(0,1)
            tmp = s[5]; s[5] = s[7]; s[7] = tmp;
            tmp = s[2]; s[2] = s[3]; s[3] = tmp;   // CNOT(1,2)
            tmp = s[6]; s[6] = s[7]; s[7] = tmp;
            ry0(qw[3 * k + 0]);
            ry1(qw[3 * k + 1]);
            ry2(qw[3 * k + 2]);
        }

        float p[8];
        #pragma unroll
        for (int i = 0; i < 8; ++i) p[i] = s[i] * s[i];

        const float z0 = (p[0] + p[1] + p[2] + p[3]) - (p[4] + p[5] + p[6] + p[7]);
        const float z1 = (p[0] + p[1] + p[4] + p[5]) - (p[2] + p[3] + p[6] + p[7]);
        const float z2 = (p[0] + p[2] + p[4] + p[6]) - (p[1] + p[3] + p[5] + p[7]);

        // ---- epilogue: this task's 8 rows x 25 float4, contiguous ----
        const int tbase = t * RB;
        if (tbase < total) {
            const int rows = min(RB, total - tbase);
            float4* __restrict__ out4 =
                reinterpret_cast<float4*>(out) + (size_t)(wbase + tbase) * 25;
            const int lim = rows * 25;
            #pragma unroll
            for (int i = 0; i < 7; ++i) {
                const int f4  = i * 32 + lane;      // 0..223 ; valid < 200
                const int row = f4 / 25;
                const int g2  = f4 - row * 25;
                const float zz0 = __shfl_sync(0xFFFFFFFFu, z0, row & 7);
                const float zz1 = __shfl_sync(0xFFFFFFFFu, z1, row & 7);
                const float zz2 = __shfl_sync(0xFFFFFFFFu, z2, row & 7);
                if (f4 < lim) {
                    const float4 f0 = __ldg(pW4 + 3 * g2 + 0);
                    const float4 f1 = __ldg(pW4 + 3 * g2 + 1);
                    const float4 f2 = __ldg(pW4 + 3 * g2 + 2);
                    const float4 bb = __ldg(pB4 + g2);
                    float4 o;
                    o.x = zz0 * f0.x + zz1 * f0.y + zz2 * f0.z + bb.x;
                    o.y = zz0 * f0.w + zz1 * f1.x + zz2 * f1.y + bb.y;
                    o.z = zz0 * f1.z + zz1 * f1.w + zz2 * f2.x + bb.z;
                    o.w = zz0 * f2.y + zz1 * f2.z + zz2 * f2.w + bb.w;
                    __stcs(out4 + f4, o);
                }
            }
        }
    }
}

extern "C" void kernel_launch(void* const* d_in, const int* in_sizes, int n_in,
                              void* d_out, int out_size)
{
    const float* X     = (const float*)d_in[0]; // [B, 512]
    const float* preW  = (const float*)d_in[1]; // [3, 512]
    const float* preB  = (const float*)d_in[2]; // [3]
    const float* qp    = (const float*)d_in[3]; // [45]
    const float* postW = (const float*)d_in[4]; // [100, 3]
    const float* postB = (const float*)d_in[5]; // [100]
    float* out = (float*)d_out;                 // [B, 100]

    const int B = in_sizes[0] / FDIM;
    const int warps  = (B + CHUNK - 1) / CHUNK;
    const int blocks = (warps + WPB - 1) / WPB;

    qnet_fused_kernel<<<blocks, WPB * 32>>>(X, preW, preB, qp, postW, postB, out, B);
}

// round 12
// speedup vs baseline: 1.2452x; 1.0471x over previous
#include <cuda_runtime.h>

#ifndef M_PI_F
#define M_PI_F 3.14159265358979323846f
#endif

#define FDIM 512
#define NOUT 100
#define RB   8             // rows per task
#define WPB  4             // warps per block (128 threads)
#define STAGES 4
#define GRID_BLOCKS 740    // 148 SMs x 5 blocks: one perfectly balanced wave

__device__ __forceinline__ void cp_async16(unsigned int saddr, const void* gaddr) {
    asm volatile("cp.async.cg.shared.global [%0], [%1], 16;" :: "r"(saddr), "l"(gaddr));
}
__device__ __forceinline__ void cp_commit() {
    asm volatile("cp.async.commit_group;" ::: "memory");
}
template <int N>
__device__ __forceinline__ void cp_wait() {
    asm volatile("cp.async.wait_group %0;" :: "n"(N) : "memory");
}
__device__ __forceinline__ unsigned long long ffma2(unsigned long long a,
                                                    unsigned long long b,
                                                    unsigned long long c) {
    unsigned long long d;
    asm("fma.rn.f32x2 %0, %1, %2, %3;" : "=l"(d) : "l"(a), "l"(b), "l"(c));
    return d;
}
__device__ __forceinline__ float f32x2_hsum(unsigned long long v) {
    float lo, hi;
    asm("mov.b64 {%0, %1}, %2;" : "=f"(lo), "=f"(hi) : "l"(v));
    return lo + hi;
}
__device__ __forceinline__ float fast_tanh(float x) {
    return 1.0f - 2.0f / (__expf(2.0f * x) + 1.0f);
}

// Persistent grid-strided warps + continuous cp.async ring:
//  - grid = 740 blocks = 148 SMs x 5 resident blocks: ONE balanced wave,
//    20 warps/SM (R10's residency) 
//  - each warp strides over 8-row tasks; the 4-deep ring issues the next
//    task's rows during this task's reduce/circuit/epilogue (R11's duty fix)
//  - per-lane self-consistent ring addressing: no cross-lane smem hazards
__global__ __launch_bounds__(128, 5)
void qnet_fused_kernel(const float* __restrict__ X,
                       const float* __restrict__ preW,
                       const float* __restrict__ preB,
                       const float* __restrict__ qp,
                       const float* __restrict__ postW,
                       const float* __restrict__ postB,
                       float* __restrict__ out,
                       int B)
{
    __shared__ float4 xring[WPB][STAGES][128];   // 32KB static

    const int tid  = threadIdx.x;
    const int wid  = tid >> 5;
    const int lane = tid & 31;

    const int n_tasks     = (B + RB - 1) / RB;
    const int warp_g      = blockIdx.x * WPB + wid;
    const int warp_stride = gridDim.x * WPB;
    if (warp_g >= n_tasks) return;
    const int n_my_tasks = (n_tasks - 1 - warp_g) / warp_stride + 1;
    const int NROWS = n_my_tasks * RB;

    const float4* __restrict__ X4 = reinterpret_cast<const float4*>(X);

    // i-th row in this warp's sequence -> global row index
    auto row_of = [&](int i) -> int {
        const int t = warp_g + (i >> 3) * warp_stride;
        return min(t * RB + (i & 7), B - 1);
    };
    auto issue = [&](int i) {
        const float4* __restrict__ src = X4 + (size_t)row_of(i) * 128;
        float4* dst = &xring[wid][i & (STAGES - 1)][0];
        #pragma unroll
        for (int k = 0; k < 4; ++k) {
            unsigned int sa = (unsigned int)__cvta_generic_to_shared(dst + lane + 32 * k);
            cp_async16(sa, src + lane + 32 * k);
        }
        cp_commit();
    };

    issue(0); issue(1); issue(2); issue(3);

    // ---- once-per-warp prolog (overlaps the first loads) ----
    const ulonglong2* __restrict__ Wp = reinterpret_cast<const ulonglong2*>(preW);
    unsigned long long w0p[8], w1p[8], w2p[8];
    #pragma unroll
    for (int k = 0; k < 4; ++k) {
        const int i = lane + 32 * k;
        ulonglong2 q0 = __ldg(Wp + i);
        ulonglong2 q1 = __ldg(Wp + 128 + i);
        ulonglong2 q2 = __ldg(Wp + 256 + i);
        w0p[2 * k] = q0.x; w0p[2 * k + 1] = q0.y;
        w1p[2 * k] = q1.x; w1p[2 * k + 1] = q1.y;
        w2p[2 * k] = q2.x; w2p[2 * k + 1] = q2.y;
    }
    const float pb0 = __ldg(preB + 0), pb1 = __ldg(preB + 1), pb2 = __ldg(preB + 2);
    float qw[6];
    #pragma unroll
    for (int j = 0; j < 6; ++j) qw[j] = __ldg(qp + 3 + j);

    const int grp  = lane >> 3;
    const int mr   = lane & 7;
    const int srcl = (mr & 3) << 3;

    const float4* __restrict__ pW4 = reinterpret_cast<const float4*>(postW);
    const float4* __restrict__ pB4 = reinterpret_cast<const float4*>(postB);

    for (int it = 0; it < n_my_tasks; ++it) {
        const int  task = warp_g + it * warp_stride;
        const int  base = task * RB;
        const bool lastTask = (it == n_my_tasks - 1);

        float c0a = 0.f, c1a = 0.f, c2a = 0.f;
        float c0b = 0.f, c1b = 0.f, c2b = 0.f;

        #pragma unroll
        for (int r = 0; r < RB; ++r) {
            const int i = it * RB + r;
            if (!lastTask || r < 5)  cp_wait<3>();
            else if (r == 5)         cp_wait<2>();
            else if (r == 6)         cp_wait<1>();
            else                     cp_wait<0>();
            __syncwarp();

            const ulonglong2* xs = reinterpret_cast<const ulonglong2*>(
                &xring[wid][i & (STAGES - 1)][0]);
            unsigned long long acc0 = 0, acc1 = 0, acc2 = 0;
            #pragma unroll
            for (int k = 0; k < 4; ++k) {
                const ulonglong2 xv = xs[lane + 32 * k];
                acc0 = ffma2(xv.x, w0p[2 * k],     acc0);
                acc0 = ffma2(xv.y, w0p[2 * k + 1], acc0);
                acc1 = ffma2(xv.x, w1p[2 * k],     acc1);
                acc1 = ffma2(xv.y, w1p[2 * k + 1], acc1);
                acc2 = ffma2(xv.x, w2p[2 * k],     acc2);
                acc2 = ffma2(xv.y, w2p[2 * k + 1], acc2);
            }
            if (!lastTask || r < 4) issue(i + 4);   // continuous across tasks

            float v0 = f32x2_hsum(acc0);
            float v1 = f32x2_hsum(acc1);
            float v2 = f32x2_hsum(acc2);

            v0 += __shfl_xor_sync(0xFFFFFFFFu, v0, 16);
            v1 += __shfl_xor_sync(0xFFFFFFFFu, v1, 16);
            v2 += __shfl_xor_sync(0xFFFFFFFFu, v2, 16);
            v0 += __shfl_xor_sync(0xFFFFFFFFu, v0, 8);
            v1 += __shfl_xor_sync(0xFFFFFFFFu, v1, 8);
            v2 += __shfl_xor_sync(0xFFFFFFFFu, v2, 8);

            const bool g = (grp == (r & 3));
            if (r < 4) {
                c0a = g ? v0 : c0a;  c1a = g ? v1 : c1a;  c2a = g ? v2 : c2a;
            } else {
                c0b = g ? v0 : c0b;  c1b = g ? v1 : c1b;  c2b = g ? v2 : c2b;
            }
        }

        #pragma unroll
        for (int off = 4; off > 0; off >>= 1) {
            c0a += __shfl_xor_sync(0xFFFFFFFFu, c0a, off);
            c1a += __shfl_xor_sync(0xFFFFFFFFu, c1a, off);
            c2a += __shfl_xor_sync(0xFFFFFFFFu, c2a, off);
            c0b += __shfl_xor_sync(0xFFFFFFFFu, c0b, off);
            c1b += __shfl_xor_sync(0xFFFFFFFFu, c1b, off);
            c2b += __shfl_xor_sync(0xFFFFFFFFu, c2b, off);
        }

        const float xa0 = __shfl_sync(0xFFFFFFFFu, c0a, srcl);
        const float xb0 = __shfl_sync(0xFFFFFFFFu, c0b, srcl);
        const float xa1 = __shfl_sync(0xFFFFFFFFu, c1a, srcl);
        const float xb1 = __shfl_sync(0xFFFFFFFFu, c1b, srcl);
        const float xa2 = __shfl_sync(0xFFFFFFFFu, c2a, srcl);
        const float xb2 = __shfl_sync(0xFFFFFFFFu, c2b, srcl);
        const float a0 = (mr < 4) ? xa0 : xb0;
        const float a1 = (mr < 4) ? xa1 : xb1;
        const float a2 = (mr < 4) ? xa2 : xb2;

        // ---- per-lane circuit ----
        const float t0 = fast_tanh(a0 + pb0) * (M_PI_F * 0.5f);
        const float t1 = fast_tanh(a1 + pb1) * (M_PI_F * 0.5f);
        const float t2 = fast_tanh(a2 + pb2) * (M_PI_F * 0.5f);

        float s[8];
        const float inv_sqrt8 = 0.3535533905932738f;
        #pragma unroll
        for (int i = 0; i < 8; ++i) s[i] = inv_sqrt8;

        auto ry0 = [&](float th) {
            float sn, cs; __sincosf(th * 0.5f, &sn, &cs);
            #pragma unroll
            for (int i = 0; i < 4; ++i) {
                float a = s[i], b = s[i + 4];
                s[i]     = cs * a - sn * b;
                s[i + 4] = sn * a + cs * b;
            }
        };
        auto ry1 = [&](float th) {
            float sn, cs; __sincosf(th * 0.5f, &sn, &cs);
            #pragma unroll
            for (int g2 = 0; g2 < 2; ++g2)
                #pragma unroll
                for (int i = 0; i < 2; ++i) {
                    int lo = g2 * 4 + i;
                    float a = s[lo], b = s[lo + 2];
                    s[lo]     = cs * a - sn * b;
                    s[lo + 2] = sn * a + cs * b;
                }
        };
        auto ry2 = [&](float th) {
            float sn, cs; __sincosf(th * 0.5f, &sn, &cs);
            #pragma unroll
            for (int g2 = 0; g2 < 4; ++g2) {
                int lo = g2 * 2;
                float a = s[lo], b = s[lo + 1];
                s[lo]     = cs * a - sn * b;
                s[lo + 1] = sn * a + cs * b;
            }
        };

        ry0(t0); ry1(t1); ry2(t2);

        #pragma unroll
        for (int k = 0; k < 2; ++k) {
            float tmp;
            tmp = s[4]; s[4] = s[6]; s[6] = tmp;   // CNOT(0,1)
            tmp = s[5]; s[5] = s[7]; s[7] = tmp;
            tmp = s[2]; s[2] = s[3]; s[3] = tmp;   // CNOT(1,2)
            tmp = s[6]; s[6] = s[7]; s[7] = tmp;
            ry0(qw[3 * k + 0]);
            ry1(qw[3 * k + 1]);
            ry2(qw[3 * k + 2]);
        }

        float p[8];
        #pragma unroll
        for (int i = 0; i < 8; ++i) p[i] = s[i] * s[i];

        const float z0 = (p[0] + p[1] + p[2] + p[3]) - (p[4] + p[5] + p[6] + p[7]);
        const float z1 = (p[0] + p[1] + p[4] + p[5]) - (p[2] + p[3] + p[6] + p[7]);
        const float z2 = (p[0] + p[2] + p[4] + p[6]) - (p[1] + p[3] + p[5] + p[7]);

        // ---- epilogue: this task's rows x 25 float4, contiguous ----
        const int rows = min(RB, B - base);
        float4* __restrict__ out4 = reinterpret_cast<float4*>(out) + (size_t)base * 25;
        const int lim = rows * 25;
        #pragma unroll
        for (int i = 0; i < 7; ++i) {
            const int f4  = i * 32 + lane;      // 0..223 ; valid < 200
            const int row = f4 / 25;
            const int g2  = f4 - row * 25;
            const float zz0 = __shfl_sync(0xFFFFFFFFu, z0, row & 7);
            const float zz1 = __shfl_sync(0xFFFFFFFFu, z1, row & 7);
            const float zz2 = __shfl_sync(0xFFFFFFFFu, z2, row & 7);
            if (f4 < lim) {
                const float4 f0 = __ldg(pW4 + 3 * g2 + 0);
                const float4 f1 = __ldg(pW4 + 3 * g2 + 1);
                const float4 f2 = __ldg(pW4 + 3 * g2 + 2);
                const float4 bb = __ldg(pB4 + g2);
                float4 o;
                o.x = zz0 * f0.x + zz1 * f0.y + zz2 * f0.z + bb.x;
                o.y = zz0 * f0.w + zz1 * f1.x + zz2 * f1.y + bb.y;
                o.z = zz0 * f1.z + zz1 * f1.w + zz2 * f2.x + bb.z;
                o.w = zz0 * f2.y + zz1 * f2.z + zz2 * f2.w + bb.w;
                __stcs(out4 + f4, o);
            }
        }
    }
}

extern "C" void kernel_launch(void* const* d_in, const int* in_sizes, int n_in,
                              void* d_out, int out_size)
{
    const float* X     = (const float*)d_in[0]; // [B, 512]
    const float* preW  = (const float*)d_in[1]; // [3, 512]
    const float* preB  = (const float*)d_in[2]; // [3]
    const float* qp    = (const float*)d_in[3]; // [45]
    const float* postW = (const float*)d_in[4]; // [100, 3]
    const float* postB = (const float*)d_in[5]; // [100]
    float* out = (float*)d_out;                 // [B, 100]

    const int B = in_sizes[0] / FDIM;
    const int n_tasks = (B + RB - 1) / RB;
    int blocks = (n_tasks + WPB - 1) / WPB;
    if (blocks > GRID_BLOCKS) blocks = GRID_BLOCKS;

    qnet_fused_kernel<<<blocks, WPB * 32>>>(X, preW, preB, qp, postW, postB, out, B);
}